// round 6
// baseline (speedup 1.0000x reference)
#include <cuda_runtime.h>
#include <cuda_fp16.h>
#include <cuda_bf16.h>

// FFT-based 2x upsample, fully-real polyphase formulation (see R2/R3/R5).
// R6: __launch_bounds__(512,2) on the FFT kernels (R5 ran 1 CTA/SM: 64 regs x
// 512 thr x 2 blocks == entire RF -> didn't fit; LDS latency unhidden at occ
// 47%). K4 writes float2 (one store per output column-pair).

#define FN    4096
#define TPB   512
#define NPAIR (FN / 2)
#define SMEM_FFT (2 * FN * sizeof(float2))   // 64 KB double-buffer

// B[i][j]  = half2(x[i][j], R_row_i[j])     (output cols 2j / 2j+1, row pass)
// Bt[j][i] = B[i][j]                         (transposed)
// R[c][i]  = half2(Ru, Rv')                  (odd output rows, cols 2c / 2c+1)
__device__ __align__(16) __half2 g_B [(size_t)FN * FN];
__device__ __align__(16) __half2 g_Bt[(size_t)FN * FN];
__device__ __align__(16) __half2 g_R [(size_t)FN * FN];
__device__ float g_Dpart[NPAIR];
__device__ float g_D[1];
// twA[k] = e^{-2 pi i k/4096}, twB[k] = e^{+i pi k/4096}, k < 512
__device__ __align__(16) float2 g_twA[512];
__device__ __align__(16) float2 g_twB[512];

__device__ __forceinline__ float2 cmul(float2 a, float2 b) {
    return make_float2(fmaf(a.x, b.x, -a.y * b.y), fmaf(a.x, b.y, a.y * b.x));
}
__device__ __forceinline__ float2 cadd(float2 a, float2 b) { return make_float2(a.x + b.x, a.y + b.y); }
__device__ __forceinline__ float2 csub(float2 a, float2 b) { return make_float2(a.x - b.x, a.y - b.y); }
__device__ __forceinline__ float2 cconj(float2 a) { return make_float2(a.x, -a.y); }

// Bank swizzle (see R3): bijective on [0,4096), conflict-free for all six
// exchange patterns (varying bits {0..3}, {0,1,2,6}, {3,4,5,6} per half-warp).
__device__ __forceinline__ int SW(int a) {
    return a ^ ((a >> 2) & 4) ^ ((a >> 4) & 2) ^ (((a >> 6) & 1) * 9);
}

__global__ void k0_twiddle() {
    int k = threadIdx.x;
    float sn, cs;
    sincospif(-(float)k / 2048.0f, &sn, &cs);
    g_twA[k] = make_float2(cs, sn);
    sincospif((float)k / 4096.0f, &sn, &cs);
    g_twB[k] = make_float2(cs, sn);
}

// Radix-8 DFT butterfly. FWD: W_8 = e^{-2pi i/8}; INV: conjugate.
template <bool INV>
__device__ __forceinline__ void bfly8(const float2 x[8], float2 y[8]) {
    float2 a0 = cadd(x[0], x[4]), a1 = csub(x[0], x[4]);
    float2 a2 = cadd(x[2], x[6]), a3 = csub(x[2], x[6]);
    float2 a4 = cadd(x[1], x[5]), a5 = csub(x[1], x[5]);
    float2 a6 = cadd(x[3], x[7]), a7 = csub(x[3], x[7]);
    float2 b0 = cadd(a0, a2), b1 = csub(a0, a2);
    float2 b2 = cadd(a4, a6), b3 = csub(a4, a6);
    float2 c3  = INV ? make_float2(-a3.y, a3.x) : make_float2(a3.y, -a3.x);
    float2 c7  = INV ? make_float2(-a7.y, a7.x) : make_float2(a7.y, -a7.x);
    float2 jb3 = INV ? make_float2(-b3.y, b3.x) : make_float2(b3.y, -b3.x);
    float2 e1 = cadd(a1, c3), e3 = csub(a1, c3);
    float2 f5 = cadd(a5, c7), f7 = csub(a5, c7);
    const float s = 0.70710678118654752440f;
    float2 W1 = INV ? make_float2(s, s)  : make_float2(s, -s);
    float2 W3 = INV ? make_float2(-s, s) : make_float2(-s, -s);
    float2 g5 = cmul(W1, f5), g7 = cmul(W3, f7);
    y[0] = cadd(b0, b2); y[4] = csub(b0, b2);
    y[2] = cadd(b1, jb3); y[6] = csub(b1, jb3);
    y[1] = cadd(e1, g5); y[5] = csub(e1, g5);
    y[3] = cadd(e3, g7); y[7] = csub(e3, g7);
}

__device__ __forceinline__ void twapply(float2 y[8], float2 w) {
    float2 wk = w;
    y[1] = cmul(y[1], wk);
    #pragma unroll
    for (int k = 2; k < 8; k++) { wk = cmul(wk, w); y[k] = cmul(y[k], wk); }
}

// S-transform: z <- N * IDFT( DFT(z) * halfshift_w ), zny <- DFT(z)[2048].
// Double-buffered: one __syncthreads() per exchange (6 total).
__device__ __forceinline__ void stransform(float2 z[8], float2* buf0, float2* buf1,
                                           float2* s_zny, int tid, float2* zny_out) {
    const int k0 = tid >> 6;
    const int s6 = tid & 63;
    const int k1 = (tid >> 3) & 7;
    const int n0 = tid & 7;
    const int m  = (tid >> 6) + 8 * ((tid >> 3) & 7) + 64 * (tid & 7);
    float2 y[8], t[8];

    const float2 w1b = __ldg(&g_twA[tid]);
    const float2 w2b = __ldg(&g_twA[8 * s6]);
    const float2 w3b = __ldg(&g_twA[64 * n0]);
    const float2 wm  = __ldg(&g_twB[m]);

    // ---- forward FFT ----
    bfly8<false>(z, y);
    twapply(y, w1b);
    #pragma unroll
    for (int q = 0; q < 8; q++) buf0[SW(512 * q + tid)] = y[q];
    __syncthreads();
    #pragma unroll
    for (int q = 0; q < 8; q++) t[q] = buf0[SW(512 * k0 + 64 * q + s6)];

    bfly8<false>(t, y);
    twapply(y, w2b);
    #pragma unroll
    for (int q = 0; q < 8; q++) buf1[SW(512 * k0 + 64 * q + s6)] = y[q];
    __syncthreads();
    #pragma unroll
    for (int q = 0; q < 8; q++) t[q] = buf1[SW(512 * k0 + 64 * k1 + 8 * q + n0)];

    bfly8<false>(t, y);
    twapply(y, w3b);
    #pragma unroll
    for (int q = 0; q < 8; q++) buf0[SW(512 * k0 + 64 * k1 + 8 * q + n0)] = y[q];
    __syncthreads();
    #pragma unroll
    for (int q = 0; q < 8; q++) t[q] = buf0[SW(8 * tid + q)];

    bfly8<false>(t, y);                         // -> X[m + 512 j]
    if (tid == 0) *s_zny = y[4];                // zny = X[2048]

    // ---- half-sample-shift phase (registers) ----
    {
        const float2 EJ[8] = {
            { 1.0f, 0.0f},
            { 0.92387953251128675613f,  0.38268343236508977173f},
            { 0.70710678118654752440f,  0.70710678118654752440f},
            { 0.38268343236508977173f,  0.92387953251128675613f},
            { 0.0f, -1.0f},
            { 0.38268343236508977173f, -0.92387953251128675613f},
            { 0.70710678118654752440f, -0.70710678118654752440f},
            { 0.92387953251128675613f, -0.38268343236508977173f}};
        #pragma unroll
        for (int j = 0; j < 8; j++) y[j] = cmul(y[j], cmul(wm, EJ[j]));
    }

    // ---- inverse FFT ----
    bfly8<true>(y, t);
    #pragma unroll
    for (int q = 0; q < 8; q++) buf1[SW(8 * tid + q)] = t[q];
    __syncthreads();
    #pragma unroll
    for (int q = 0; q < 8; q++) t[q] = buf1[SW(512 * k0 + 64 * k1 + 8 * q + n0)];

    twapply(t, cconj(w3b));
    bfly8<true>(t, y);
    #pragma unroll
    for (int q = 0; q < 8; q++) buf0[SW(512 * k0 + 64 * k1 + 8 * q + n0)] = y[q];
    __syncthreads();
    #pragma unroll
    for (int q = 0; q < 8; q++) t[q] = buf0[SW(512 * k0 + 64 * q + s6)];

    twapply(t, cconj(w2b));
    bfly8<true>(t, y);
    #pragma unroll
    for (int q = 0; q < 8; q++) buf1[SW(512 * k0 + 64 * q + s6)] = y[q];
    __syncthreads();
    #pragma unroll
    for (int q = 0; q < 8; q++) t[q] = buf1[SW(512 * q + tid)];

    twapply(t, cconj(w1b));
    bfly8<true>(t, z);                          // z[n3] = N*S[tid+512 n3]

    *zny_out = *s_zny;                          // >= 3 syncs after the write
}

// K1: 2-for-1 row pass (block r handles input rows 2r, 2r+1).
__global__ __launch_bounds__(TPB, 2) void k1_rowpass(const float* __restrict__ x) {
    extern __shared__ float2 dsm[];
    __shared__ float2 s_zny;
    float2* buf0 = dsm;
    float2* buf1 = dsm + FN;
    int tid = threadIdx.x;
    size_t r = blockIdx.x;
    const float* u = x + (2 * r) * (size_t)FN;
    const float* v = u + FN;
    float2 z[8], z0[8];
    #pragma unroll
    for (int e = 0; e < 8; e++) {
        int j = tid + e * TPB;
        z[e] = make_float2(u[j], v[j]);
        z0[e] = z[e];
    }
    float2 zny;
    stransform(z, buf0, buf1, &s_zny, tid, &zny);
    if (tid == 0) g_Dpart[r] = zny.x - zny.y;

    const float invN = 1.0f / 4096.0f;
    float sgn = (tid & 1) ? -1.0f : 1.0f;       // (-1)^j
    __half2* row0 = g_B + (2 * r) * (size_t)FN;
    __half2* row1 = row0 + FN;
    #pragma unroll
    for (int e = 0; e < 8; e++) {
        int j = tid + e * TPB;
        float Ru = (z[e].x - sgn * zny.y) * invN;
        float Rv = (z[e].y + sgn * zny.x) * invN;
        row0[j] = __floats2half2_rn(z0[e].x, Ru);
        row1[j] = __floats2half2_rn(z0[e].y, Rv);
    }
}

// Deterministic reduction of g_Dpart -> g_D.
__global__ void k_reduce() {
    __shared__ float sh[TPB];
    float s = 0.0f;
    for (int i = threadIdx.x; i < NPAIR; i += TPB) s += g_Dpart[i];
    sh[threadIdx.x] = s;
    __syncthreads();
    for (int o = TPB / 2; o > 0; o >>= 1) {
        if (threadIdx.x < o) sh[threadIdx.x] += sh[threadIdx.x + o];
        __syncthreads();
    }
    if (threadIdx.x == 0) g_D[0] = sh[0];
}

// K2: transpose B [4096x4096 half2] -> Bt.
__global__ void k2_transpose() {
    __shared__ __half2 tile[32][33];
    int tx = threadIdx.x, ty = threadIdx.y;
    int cx = blockIdx.x * 32 + tx;
    int ry = blockIdx.y * 32 + ty;
    #pragma unroll
    for (int j = 0; j < 32; j += 8)
        tile[ty + j][tx] = g_B[(size_t)(ry + j) * FN + cx];
    __syncthreads();
    int ox = blockIdx.y * 32 + tx;
    int oy = blockIdx.x * 32 + ty;
    #pragma unroll
    for (int j = 0; j < 32; j += 8)
        g_Bt[(size_t)(oy + j) * FN + ox] = tile[tx][ty + j];
}

// K3: 2-for-1 column pass (block c handles output columns 2c, 2c+1).
// Writes ONLY the odd-row values: R[c][i] = (Ru, Rv + parity corr).
__global__ __launch_bounds__(TPB, 2) void k3_colpass() {
    extern __shared__ float2 dsm[];
    __shared__ float2 s_zny;
    float2* buf0 = dsm;
    float2* buf1 = dsm + FN;
    int tid = threadIdx.x;
    size_t c = blockIdx.x;
    const __half2* bt = g_Bt + c * (size_t)FN;
    float2 z[8];
    #pragma unroll
    for (int e = 0; e < 8; e++) {
        int j = tid + e * TPB;
        z[e] = __half22float2(bt[j]);
    }
    float2 zny;
    stransform(z, buf0, buf1, &s_zny, tid, &zny);

    const float invN = 1.0f / 4096.0f;
    float corr = -g_D[0] * invN * invN;         // -D/N^2
    float sgnc = (c & 1) ? -corr : corr;        // (-1)^c * corr
    float sgn = (tid & 1) ? -1.0f : 1.0f;       // (-1)^i
    __half2* rr = g_R + c * (size_t)FN;
    #pragma unroll
    for (int e = 0; e < 8; e++) {
        int j = tid + e * TPB;
        float Ru = (z[e].x - sgn * zny.y) * invN;
        float Rv = (z[e].y + sgn * zny.x) * invN;
        rr[j] = __floats2half2_rn(Ru, Rv + sgn * sgnc);
    }
}

// K4: assemble output from Bt + R, one float2 store per column-pair.
//   out[2i  ][2c..2c+1] = float2(Bt[c][i])
//   out[2i+1][2c..2c+1] = float2(R [c][i])
__global__ void k4_assemble(float* __restrict__ out) {
    __shared__ __half2 tB[32][33];
    __shared__ __half2 tR[32][33];
    int tx = threadIdx.x, ty = threadIdx.y;    // 32 x 8
    int ib = blockIdx.x * 32;                  // i tile
    int cb = blockIdx.y * 32;                  // c tile
    #pragma unroll
    for (int j = 0; j < 32; j += 8) {
        tB[ty + j][tx] = g_Bt[(size_t)(cb + ty + j) * FN + ib + tx];
        tR[ty + j][tx] = g_R [(size_t)(cb + ty + j) * FN + ib + tx];
    }
    __syncthreads();
    float2* o2 = reinterpret_cast<float2*>(out);   // row stride 4096 float2
    #pragma unroll
    for (int j = 0; j < 32; j += 8) {
        int i_loc = ty + j;
        size_t ig = (size_t)(ib + i_loc);
        int cg = cb + tx;
        o2[(2 * ig) * 4096 + cg]     = __half22float2(tB[tx][i_loc]);
        o2[(2 * ig + 1) * 4096 + cg] = __half22float2(tR[tx][i_loc]);
    }
}

extern "C" void kernel_launch(void* const* d_in, const int* in_sizes, int n_in,
                              void* d_out, int out_size) {
    const float* x = (const float*)d_in[0];
    float* out = (float*)d_out;
    (void)in_sizes; (void)n_in; (void)out_size;

    cudaFuncSetAttribute(k1_rowpass, cudaFuncAttributeMaxDynamicSharedMemorySize,
                         (int)SMEM_FFT);
    cudaFuncSetAttribute(k3_colpass, cudaFuncAttributeMaxDynamicSharedMemorySize,
                         (int)SMEM_FFT);

    k0_twiddle<<<1, 512>>>();
    k1_rowpass<<<NPAIR, TPB, SMEM_FFT>>>(x);
    k_reduce<<<1, TPB>>>();
    k2_transpose<<<dim3(FN / 32, FN / 32), dim3(32, 8)>>>();
    k3_colpass<<<FN, TPB, SMEM_FFT>>>();
    k4_assemble<<<dim3(FN / 32, FN / 32), dim3(32, 8)>>>(out);
}